// round 15
// baseline (speedup 1.0000x reference)
#include <cuda_runtime.h>
#include <cuda_fp16.h>
#include <stdint.h>

#define NB   32
#define NT   512
#define HID  1024
#define NOUT 1024
#define NCTA     128
#define NTHREADS 256
#define SLOT_H   32768          // halfs per ring slot (32*1024)
#define XSLOT    16384          // halfs per x slot (32*512)

// ---------------- static device scratch ----------------
__device__ __align__(16) __half  g_xfrag[(size_t)NT * XSLOT];          // x, frag2 layout
__device__ __align__(16) __half  g_ringA[(size_t)(NT + 1) * SLOT_H];   // h rings, frag2 layout
__device__ __align__(16) __half  g_ringB[(size_t)(NT + 1) * SLOT_H];
__device__ __align__(16) __half  g_WT[(size_t)4096 * (1536 + 3 * 2048)]; // W^T fp16 [n][Ktot]
__device__ __align__(16) float   g_Z0[(size_t)NT * NB * 4096];         // input-part preacts
__device__ __align__(16) float   g_hlast[NB * HID];
// 8 per-K-slice counters (one per producer group of 16 CTAs), 128B apart
__device__ __align__(128) unsigned g_cnt[8 * 32];

__global__ void reset_kernel() {
    int i = threadIdx.x;
    if (i < 8 * 32) g_cnt[i] = 0u;
}

__device__ __forceinline__ unsigned ld_acq(const unsigned* p) {
    unsigned v;
    asm volatile("ld.global.acquire.gpu.u32 %0, [%1];" : "=r"(v) : "l"(p) : "memory");
    return v;
}
__device__ __forceinline__ void red_rel(unsigned* p) {
    asm volatile("red.global.release.gpu.add.u32 [%0], 1;" :: "l"(p) : "memory");
}

__device__ __forceinline__ float sigmoid_fast(float x) {
    return __fdividef(1.f, 1.f + __expf(-x));   // MUFU path, no div.rn
}
__device__ __forceinline__ float tanh_fast(float x) {
    float e = __expf(2.f * x);                  // saturates correctly at +/-inf
    return 1.f - __fdividef(2.f, e + 1.f);
}

__device__ __forceinline__ void mma16816(float* c, const uint32_t* a, const uint32_t* b) {
    asm volatile(
        "mma.sync.aligned.m16n8k16.row.col.f32.f16.f16.f32 "
        "{%0,%1,%2,%3},{%4,%5,%6,%7},{%8,%9},{%0,%1,%2,%3};\n"
        : "+f"(c[0]), "+f"(c[1]), "+f"(c[2]), "+f"(c[3])
        : "r"(a[0]), "r"(a[1]), "r"(a[2]), "r"(a[3]), "r"(b[0]), "r"(b[1]));
}
__device__ __forceinline__ void cp16(void* s, const void* g) {
    uint32_t a = (uint32_t)__cvta_generic_to_shared(s);
    asm volatile("cp.async.cg.shared.global [%0], [%1], 16;\n" :: "r"(a), "l"(g));
}
__device__ __forceinline__ void cpcommit() { asm volatile("cp.async.commit_group;\n"); }
__device__ __forceinline__ void cpwait0()  { asm volatile("cp.async.wait_group 0;\n"); }

// frag2 layout (warp-coalesced, validated R7+): chunk-major.
__device__ __forceinline__ size_t frag2_off(int b, int k) {
    int w = k >> 7, kp = k & 127;
    int it = kp >> 4, kw = kp & 15;
    int tig = (kw >> 1) & 3, ps = kw >> 3, bit = kw & 1;
    int g = b & 7, rh = (b >> 3) & 1, mh = b >> 4;
    return (size_t)w * 4096 + (size_t)(it * 2 + mh) * 256
         + (size_t)(g * 4 + tig) * 8 + (size_t)(ps * 2 + rh) * 2 + bit;
}

// x[B][T][512] f32 -> g_xfrag frag2 layout; one 16B chunk per thread
__global__ void xfrag_kernel(const float* __restrict__ x) {
    int c = blockIdx.x * blockDim.x + threadIdx.x;   // NT*2048 chunks
    int lane = c & 31, i = (c >> 5) & 15, wid = (c >> 9) & 3, t = c >> 11;
    int it = i >> 1, mh = i & 1, g = lane >> 2, tig = lane & 3;
    __half h[8];
    #pragma unroll
    for (int reg = 0; reg < 4; ++reg) {
        int ps = reg >> 1, rh = reg & 1;
        int b = mh * 16 + rh * 8 + g;
        int k = wid * 128 + it * 16 + ps * 8 + 2 * tig;
        float2 v = *(const float2*)(x + ((size_t)b * NT + t) * 512 + k);
        h[reg * 2]     = __float2half(v.x);
        h[reg * 2 + 1] = __float2half(v.y);
    }
    *(uint4*)(g_xfrag + (size_t)t * XSLOT + (size_t)wid * 4096
              + (size_t)i * 256 + (size_t)lane * 8) = *(const uint4*)h;
}

// W (f32 [Ktot][4096]) -> g_WT (fp16 [4096][Ktot]), all 4 layers
__global__ void convT_kernel(const float* __restrict__ W0, const float* __restrict__ Wl) {
    __shared__ float ts[32][33];
    int bid = blockIdx.x;
    const float* src; size_t wtoff; int Ktot, tile;
    if (bid < 6144) { src = W0; wtoff = 0; Ktot = 1536; tile = bid; }
    else {
        int r = bid - 6144, l = r / 8192; tile = r % 8192;
        src = Wl + (size_t)l * 2048 * 4096;
        wtoff = (size_t)4096 * 1536 + (size_t)l * 4096 * 2048; Ktot = 2048;
    }
    int tk = tile >> 7, tn = tile & 127;
    int tx = threadIdx.x & 31, ty = threadIdx.x >> 5;
    #pragma unroll
    for (int r = 0; r < 4; ++r)
        ts[ty + r * 8][tx] = src[(size_t)(tk * 32 + ty + r * 8) * 4096 + tn * 32 + tx];
    __syncthreads();
    #pragma unroll
    for (int r = 0; r < 4; ++r)
        g_WT[wtoff + (size_t)(tn * 32 + ty + r * 8) * Ktot + tk * 32 + tx] =
            __float2half(ts[tx][ty + r * 8]);
}

// batch GEMM (R11-identical): Z0[m][n] = A(frag2) @ WT^T + bias
__global__ __launch_bounds__(256, 2)
void gemm_kernel(int srcsel, int aslot, size_t wtoff, int KtotS, int Kin,
                 const float* __restrict__ bias) {
    __shared__ __half sB[2][128 * 40];
    const __half* A = (srcsel == 0) ? g_xfrag
                    : (srcsel == 1) ? (g_ringA + SLOT_H) : (g_ringB + SLOT_H);
    const __half* BT = g_WT + wtoff;
    const int tid = threadIdx.x;
    const int bm = blockIdx.x & 127, bn = blockIdx.x >> 7;
    const int wid = tid >> 5, lane = tid & 31;
    const int g = lane >> 2, tig = lane & 3;
    const int wm = wid & 3, wn = wid >> 2;
    const int tg = bm * 4 + wm;

    float acc[2][8][4];
    #pragma unroll
    for (int i = 0; i < 2; ++i)
        #pragma unroll
        for (int j = 0; j < 8; ++j)
            #pragma unroll
            for (int k = 0; k < 4; ++k) acc[i][j][k] = 0.f;

    const __half* abase = A + (size_t)tg * aslot + (size_t)lane * 8;
    const int niter = Kin >> 5;
    auto loadB = [&](int buf, int kt) {
        #pragma unroll
        for (int i = 0; i < 2; ++i) {
            int o = tid + i * 256, n = o >> 2, jl = o & 3;
            cp16(&sB[buf][n * 40 + jl * 8],
                 BT + (size_t)(bn * 128 + n) * KtotS + kt * 32 + jl * 8);
        }
    };
    auto loadA = [&](uint4 af[2][2], int kt) {
        const __half* ap = abase + (size_t)(kt >> 2) * 4096 + (size_t)(kt & 3) * 1024;
        af[0][0] = __ldcg((const uint4*)(ap));
        af[0][1] = __ldcg((const uint4*)(ap + 256));
        af[1][0] = __ldcg((const uint4*)(ap + 512));
        af[1][1] = __ldcg((const uint4*)(ap + 768));
    };

    uint4 afr[2][2], afn[2][2];
    loadB(0, 0); cpcommit();
    loadA(afr, 0);
    for (int kt = 0; kt < niter; ++kt) {
        int buf = kt & 1;
        if (kt + 1 < niter) loadA(afn, kt + 1);
        cpwait0();
        __syncthreads();
        if (kt + 1 < niter) { loadB(buf ^ 1, kt + 1); cpcommit(); }
        #pragma unroll
        for (int ks = 0; ks < 2; ++ks) {
            const int kk = ks * 16;
            uint32_t b[8][2];
            #pragma unroll
            for (int nt = 0; nt < 8; ++nt) {
                const __half* bp = &sB[buf][(wn * 64 + nt * 8 + g) * 40 + kk + 2 * tig];
                b[nt][0] = *(const uint32_t*)(bp);
                b[nt][1] = *(const uint32_t*)(bp + 8);
            }
            #pragma unroll
            for (int nt = 0; nt < 8; ++nt) {
                mma16816(acc[0][nt], (const uint32_t*)&afr[ks][0], b[nt]);
                mma16816(acc[1][nt], (const uint32_t*)&afr[ks][1], b[nt]);
            }
        }
        #pragma unroll
        for (int ks = 0; ks < 2; ++ks) { afr[ks][0] = afn[ks][0]; afr[ks][1] = afn[ks][1]; }
    }
    #pragma unroll
    for (int mt = 0; mt < 2; ++mt)
        #pragma unroll
        for (int nt = 0; nt < 8; ++nt) {
            int r0 = tg * 32 + mt * 16 + g;
            int c0 = bn * 128 + wn * 64 + nt * 8 + 2 * tig;
            float b0v = bias[c0], b1v = bias[c0 + 1];
            *(float2*)(g_Z0 + (size_t)r0 * 4096 + c0) =
                make_float2(acc[mt][nt][0] + b0v, acc[mt][nt][1] + b1v);
            *(float2*)(g_Z0 + (size_t)(r0 + 8) * 4096 + c0) =
                make_float2(acc[mt][nt][2] + b0v, acc[mt][nt][3] + b1v);
        }
}

// persistent recurrent loop — R11-identical
__global__ __launch_bounds__(NTHREADS, 1)
void loop_kernel(int ringsel, const float* __restrict__ h0l, const float* __restrict__ c0l,
                 size_t wtoff, int KtotS, int Kin, int lastflag, unsigned barbase) {
    __shared__ float partials[8 * 1152];    // 8 warps x (32 rows x 36 stride)
    __half* ring = ringsel ? g_ringB : g_ringA;
    const __half* WT_l = g_WT + wtoff;

    const int tid = threadIdx.x, cta = blockIdx.x;
    const int wid = tid >> 5, lane = tid & 31;
    const int g = lane >> 2, tig = lane & 3;
    const int rb = tid >> 3, rd = tid & 7;

    uint32_t wreg[8][4][2];
    #pragma unroll
    for (int it = 0; it < 8; ++it)
        #pragma unroll
        for (int nt = 0; nt < 4; ++nt) {
            const __half* p = WT_l + (size_t)(nt * HID + cta * 8 + g) * KtotS
                            + Kin + wid * 128 + it * 16 + 2 * tig;
            wreg[it][nt][0] = *(const uint32_t*)(p);
            wreg[it][nt][1] = *(const uint32_t*)(p + 8);
        }

    float c_state = c0l[rb * HID + cta * 8 + rd];
    const size_t pofs = frag2_off(rb, cta * 8 + rd);
    const size_t cofs = (size_t)wid * 4096 + (size_t)lane * 8;
    unsigned* mycnt = &g_cnt[(cta >> 4) * 32];
    const unsigned* wcnt = &g_cnt[wid * 32];

    ring[pofs] = __float2half(h0l[rb * HID + cta * 8 + rd]);
    __syncthreads();
    if (tid == 0) red_rel(mycnt);
    unsigned wtarget = barbase + 16;

    size_t slot = SLOT_H;
    for (int t = 0; t < NT; ++t, slot += SLOT_H) {
        float z0r[4];
        {
            const float* zp = g_Z0 + ((size_t)(t * NB + rb)) * 4096 + cta * 8 + rd;
            #pragma unroll
            for (int gg = 0; gg < 4; ++gg) z0r[gg] = __ldcg(zp + gg * HID);
        }

        if (lane == 0) { while (ld_acq(wcnt) < wtarget) { } }
        __syncwarp();

        const __half* hp = ring + (slot - SLOT_H) + cofs;
        uint4 areg[16];
        #pragma unroll
        for (int i = 0; i < 16; ++i) areg[i] = __ldcg((const uint4*)(hp + (size_t)i * 256));

        float acc[2][4][4];
        #pragma unroll
        for (int i = 0; i < 2; ++i)
            #pragma unroll
            for (int j = 0; j < 4; ++j)
                #pragma unroll
                for (int k = 0; k < 4; ++k) acc[i][j][k] = 0.f;
        #pragma unroll
        for (int it = 0; it < 8; ++it) {
            const uint32_t* a0 = (const uint32_t*)&areg[it * 2];
            const uint32_t* a1 = (const uint32_t*)&areg[it * 2 + 1];
            #pragma unroll
            for (int nt = 0; nt < 4; ++nt) {
                mma16816(acc[0][nt], a0, wreg[it][nt]);
                mma16816(acc[1][nt], a1, wreg[it][nt]);
            }
        }

        {
            float* P = partials + wid * 1152;
            #pragma unroll
            for (int mt = 0; mt < 2; ++mt)
                #pragma unroll
                for (int nt = 0; nt < 4; ++nt) {
                    int r = mt * 16 + g, cc = nt * 8 + 2 * tig;
                    *(float2*)(P + r * 36 + cc) = make_float2(acc[mt][nt][0], acc[mt][nt][1]);
                    *(float2*)(P + (r + 8) * 36 + cc) = make_float2(acc[mt][nt][2], acc[mt][nt][3]);
                }
        }
        __syncthreads();

        {
            float zi = z0r[0], zf = z0r[1], zg = z0r[2], zo = z0r[3];
            #pragma unroll
            for (int w = 0; w < 8; ++w) {
                const float* P = partials + w * 1152 + rb * 36 + rd;
                zi += P[0]; zf += P[8]; zg += P[16]; zo += P[24];
            }
            float si = sigmoid_fast(zi);
            float sf = sigmoid_fast(zf);
            float so = sigmoid_fast(zo);
            float tg2 = tanh_fast(zg);
            c_state = sf * c_state + si * tg2;
            float h = so * tanh_fast(c_state);
            ring[slot + pofs] = __float2half(h);
            if (lastflag && t == NT - 1) g_hlast[rb * HID + cta * 8 + rd] = h;
        }
        __syncthreads();
        if (tid == 0) red_rel(mycnt);
        wtarget += 16;
    }
}

// dense head v2: one block per batch row; float4 coalesced Wout rows; smem-broadcast h
__global__ __launch_bounds__(256)
void head_kernel(const float* __restrict__ Wout,
                 const float* __restrict__ bout,
                 float* __restrict__ out) {
    __shared__ float hsh[HID];
    int b = blockIdx.x;
    for (int i = threadIdx.x; i < HID; i += blockDim.x) hsh[i] = g_hlast[b * HID + i];
    __syncthreads();
    int o = threadIdx.x * 4;                   // 256 threads x 4 outputs
    float4 acc = *(const float4*)(bout + o);
    #pragma unroll 4
    for (int k = 0; k < HID; ++k) {
        float hv = hsh[k];
        float4 w = *(const float4*)(Wout + (size_t)k * NOUT + o);
        acc.x += hv * w.x; acc.y += hv * w.y;
        acc.z += hv * w.z; acc.w += hv * w.w;
    }
    *(float4*)(out + (size_t)b * NOUT + o) = acc;
}

extern "C" void kernel_launch(void* const* d_in, const int* in_sizes, int n_in,
                              void* d_out, int out_size) {
    const float* x    = (const float*)d_in[0];
    const float* h0   = (const float*)d_in[1];
    const float* c0   = (const float*)d_in[2];
    const float* W0   = (const float*)d_in[3];
    const float* b0   = (const float*)d_in[4];
    const float* Wl   = (const float*)d_in[5];
    const float* bl   = (const float*)d_in[6];
    const float* Wout = (const float*)d_in[7];
    const float* bout = (const float*)d_in[8];
    float* out = (float*)d_out;

    const size_t HB = (size_t)NB * HID;
    const size_t wt0 = 0;
    const size_t wt1 = (size_t)4096 * 1536;
    const size_t wt2 = wt1 + (size_t)4096 * 2048;
    const size_t wt3 = wt2 + (size_t)4096 * 2048;
    const unsigned per = (unsigned)((NT + 1) * 16);

    reset_kernel<<<1, 256>>>();
    xfrag_kernel<<<4096, 256>>>(x);
    convT_kernel<<<30720, 256>>>(W0, Wl);

    // layer 0
    gemm_kernel<<<4096, 256>>>(0, XSLOT, wt0, 1536, 512, b0);
    loop_kernel<<<NCTA, NTHREADS>>>(0, h0, c0, wt0, 1536, 512, 0, 0 * per);
    // layer 1 (input = ringA)
    gemm_kernel<<<4096, 256>>>(1, SLOT_H, wt1, 2048, 1024, bl);
    loop_kernel<<<NCTA, NTHREADS>>>(1, h0 + HB, c0 + HB, wt1, 2048, 1024, 0, 1 * per);
    // layer 2 (input = ringB)
    gemm_kernel<<<4096, 256>>>(2, SLOT_H, wt2, 2048, 1024, bl + 4096);
    loop_kernel<<<NCTA, NTHREADS>>>(0, h0 + 2 * HB, c0 + 2 * HB, wt2, 2048, 1024, 0, 2 * per);
    // layer 3 (input = ringA)
    gemm_kernel<<<4096, 256>>>(1, SLOT_H, wt3, 2048, 1024, bl + 2 * 4096);
    loop_kernel<<<NCTA, NTHREADS>>>(1, h0 + 3 * HB, c0 + 3 * HB, wt3, 2048, 1024, 1, 3 * per);

    head_kernel<<<NB, 256>>>(Wout, bout, out);
}

// round 16
// speedup vs baseline: 1.0320x; 1.0320x over previous
#include <cuda_runtime.h>
#include <cuda_fp16.h>
#include <stdint.h>

#define NB   32
#define NT   512
#define HID  1024
#define NOUT 1024
#define NCTA     128
#define NTHREADS 256
#define SLOT_H   32768          // halfs per ring slot (32*1024)
#define XSLOT    16384          // halfs per x slot (32*512)

// ---------------- static device scratch ----------------
__device__ __align__(16) __half  g_xfrag[(size_t)NT * XSLOT];          // x, frag2 layout
__device__ __align__(16) __half  g_ringA[(size_t)(NT + 1) * SLOT_H];   // h rings, frag2 layout
__device__ __align__(16) __half  g_ringB[(size_t)(NT + 1) * SLOT_H];
__device__ __align__(16) __half  g_WT[(size_t)4096 * (1536 + 3 * 2048)]; // W^T fp16 [n][Ktot]
__device__ __align__(16) float   g_Z0[(size_t)NT * NB * 4096];         // input-part preacts
__device__ __align__(16) float   g_hlast[NB * HID];
// 8 per-K-slice counters (one per producer group of 16 CTAs), 128B apart
__device__ __align__(128) unsigned g_cnt[8 * 32];

__global__ void reset_kernel() {
    int i = threadIdx.x;
    if (i < 8 * 32) g_cnt[i] = 0u;
}
// no-op spacer: shifts ncu's "-s 5 -c 1" capture window onto loop_kernel
__global__ void spacer_kernel() { }

__device__ __forceinline__ unsigned ld_acq(const unsigned* p) {
    unsigned v;
    asm volatile("ld.global.acquire.gpu.u32 %0, [%1];" : "=r"(v) : "l"(p) : "memory");
    return v;
}
__device__ __forceinline__ void red_rel(unsigned* p) {
    asm volatile("red.global.release.gpu.add.u32 [%0], 1;" :: "l"(p) : "memory");
}

__device__ __forceinline__ float sigmoid_fast(float x) {
    return __fdividef(1.f, 1.f + __expf(-x));   // MUFU path, no div.rn
}
__device__ __forceinline__ float tanh_fast(float x) {
    float e = __expf(2.f * x);                  // saturates correctly at +/-inf
    return 1.f - __fdividef(2.f, e + 1.f);
}

__device__ __forceinline__ void mma16816(float* c, const uint32_t* a, const uint32_t* b) {
    asm volatile(
        "mma.sync.aligned.m16n8k16.row.col.f32.f16.f16.f32 "
        "{%0,%1,%2,%3},{%4,%5,%6,%7},{%8,%9},{%0,%1,%2,%3};\n"
        : "+f"(c[0]), "+f"(c[1]), "+f"(c[2]), "+f"(c[3])
        : "r"(a[0]), "r"(a[1]), "r"(a[2]), "r"(a[3]), "r"(b[0]), "r"(b[1]));
}
__device__ __forceinline__ void cp16(void* s, const void* g) {
    uint32_t a = (uint32_t)__cvta_generic_to_shared(s);
    asm volatile("cp.async.cg.shared.global [%0], [%1], 16;\n" :: "r"(a), "l"(g));
}
__device__ __forceinline__ void cpcommit() { asm volatile("cp.async.commit_group;\n"); }
__device__ __forceinline__ void cpwait0()  { asm volatile("cp.async.wait_group 0;\n"); }

// frag2 layout (warp-coalesced, validated R7+): chunk-major.
__device__ __forceinline__ size_t frag2_off(int b, int k) {
    int w = k >> 7, kp = k & 127;
    int it = kp >> 4, kw = kp & 15;
    int tig = (kw >> 1) & 3, ps = kw >> 3, bit = kw & 1;
    int g = b & 7, rh = (b >> 3) & 1, mh = b >> 4;
    return (size_t)w * 4096 + (size_t)(it * 2 + mh) * 256
         + (size_t)(g * 4 + tig) * 8 + (size_t)(ps * 2 + rh) * 2 + bit;
}

// x[B][T][512] f32 -> g_xfrag frag2 layout; one 16B chunk per thread
__global__ void xfrag_kernel(const float* __restrict__ x) {
    int c = blockIdx.x * blockDim.x + threadIdx.x;   // NT*2048 chunks
    int lane = c & 31, i = (c >> 5) & 15, wid = (c >> 9) & 3, t = c >> 11;
    int it = i >> 1, mh = i & 1, g = lane >> 2, tig = lane & 3;
    __half h[8];
    #pragma unroll
    for (int reg = 0; reg < 4; ++reg) {
        int ps = reg >> 1, rh = reg & 1;
        int b = mh * 16 + rh * 8 + g;
        int k = wid * 128 + it * 16 + ps * 8 + 2 * tig;
        float2 v = *(const float2*)(x + ((size_t)b * NT + t) * 512 + k);
        h[reg * 2]     = __float2half(v.x);
        h[reg * 2 + 1] = __float2half(v.y);
    }
    *(uint4*)(g_xfrag + (size_t)t * XSLOT + (size_t)wid * 4096
              + (size_t)i * 256 + (size_t)lane * 8) = *(const uint4*)h;
}

// W (f32 [Ktot][4096]) -> g_WT (fp16 [4096][Ktot]), all 4 layers
__global__ void convT_kernel(const float* __restrict__ W0, const float* __restrict__ Wl) {
    __shared__ float ts[32][33];
    int bid = blockIdx.x;
    const float* src; size_t wtoff; int Ktot, tile;
    if (bid < 6144) { src = W0; wtoff = 0; Ktot = 1536; tile = bid; }
    else {
        int r = bid - 6144, l = r / 8192; tile = r % 8192;
        src = Wl + (size_t)l * 2048 * 4096;
        wtoff = (size_t)4096 * 1536 + (size_t)l * 4096 * 2048; Ktot = 2048;
    }
    int tk = tile >> 7, tn = tile & 127;
    int tx = threadIdx.x & 31, ty = threadIdx.x >> 5;
    #pragma unroll
    for (int r = 0; r < 4; ++r)
        ts[ty + r * 8][tx] = src[(size_t)(tk * 32 + ty + r * 8) * 4096 + tn * 32 + tx];
    __syncthreads();
    #pragma unroll
    for (int r = 0; r < 4; ++r)
        g_WT[wtoff + (size_t)(tn * 32 + ty + r * 8) * Ktot + tk * 32 + tx] =
            __float2half(ts[tx][ty + r * 8]);
}

// batch GEMM (R11-identical): Z0[m][n] = A(frag2) @ WT^T + bias
__global__ __launch_bounds__(256, 2)
void gemm_kernel(int srcsel, int aslot, size_t wtoff, int KtotS, int Kin,
                 const float* __restrict__ bias) {
    __shared__ __half sB[2][128 * 40];
    const __half* A = (srcsel == 0) ? g_xfrag
                    : (srcsel == 1) ? (g_ringA + SLOT_H) : (g_ringB + SLOT_H);
    const __half* BT = g_WT + wtoff;
    const int tid = threadIdx.x;
    const int bm = blockIdx.x & 127, bn = blockIdx.x >> 7;
    const int wid = tid >> 5, lane = tid & 31;
    const int g = lane >> 2, tig = lane & 3;
    const int wm = wid & 3, wn = wid >> 2;
    const int tg = bm * 4 + wm;

    float acc[2][8][4];
    #pragma unroll
    for (int i = 0; i < 2; ++i)
        #pragma unroll
        for (int j = 0; j < 8; ++j)
            #pragma unroll
            for (int k = 0; k < 4; ++k) acc[i][j][k] = 0.f;

    const __half* abase = A + (size_t)tg * aslot + (size_t)lane * 8;
    const int niter = Kin >> 5;
    auto loadB = [&](int buf, int kt) {
        #pragma unroll
        for (int i = 0; i < 2; ++i) {
            int o = tid + i * 256, n = o >> 2, jl = o & 3;
            cp16(&sB[buf][n * 40 + jl * 8],
                 BT + (size_t)(bn * 128 + n) * KtotS + kt * 32 + jl * 8);
        }
    };
    auto loadA = [&](uint4 af[2][2], int kt) {
        const __half* ap = abase + (size_t)(kt >> 2) * 4096 + (size_t)(kt & 3) * 1024;
        af[0][0] = __ldcg((const uint4*)(ap));
        af[0][1] = __ldcg((const uint4*)(ap + 256));
        af[1][0] = __ldcg((const uint4*)(ap + 512));
        af[1][1] = __ldcg((const uint4*)(ap + 768));
    };

    uint4 afr[2][2], afn[2][2];
    loadB(0, 0); cpcommit();
    loadA(afr, 0);
    for (int kt = 0; kt < niter; ++kt) {
        int buf = kt & 1;
        if (kt + 1 < niter) loadA(afn, kt + 1);
        cpwait0();
        __syncthreads();
        if (kt + 1 < niter) { loadB(buf ^ 1, kt + 1); cpcommit(); }
        #pragma unroll
        for (int ks = 0; ks < 2; ++ks) {
            const int kk = ks * 16;
            uint32_t b[8][2];
            #pragma unroll
            for (int nt = 0; nt < 8; ++nt) {
                const __half* bp = &sB[buf][(wn * 64 + nt * 8 + g) * 40 + kk + 2 * tig];
                b[nt][0] = *(const uint32_t*)(bp);
                b[nt][1] = *(const uint32_t*)(bp + 8);
            }
            #pragma unroll
            for (int nt = 0; nt < 8; ++nt) {
                mma16816(acc[0][nt], (const uint32_t*)&afr[ks][0], b[nt]);
                mma16816(acc[1][nt], (const uint32_t*)&afr[ks][1], b[nt]);
            }
        }
        #pragma unroll
        for (int ks = 0; ks < 2; ++ks) { afr[ks][0] = afn[ks][0]; afr[ks][1] = afn[ks][1]; }
    }
    #pragma unroll
    for (int mt = 0; mt < 2; ++mt)
        #pragma unroll
        for (int nt = 0; nt < 8; ++nt) {
            int r0 = tg * 32 + mt * 16 + g;
            int c0 = bn * 128 + wn * 64 + nt * 8 + 2 * tig;
            float b0v = bias[c0], b1v = bias[c0 + 1];
            *(float2*)(g_Z0 + (size_t)r0 * 4096 + c0) =
                make_float2(acc[mt][nt][0] + b0v, acc[mt][nt][1] + b1v);
            *(float2*)(g_Z0 + (size_t)(r0 + 8) * 4096 + c0) =
                make_float2(acc[mt][nt][2] + b0v, acc[mt][nt][3] + b1v);
        }
}

// persistent recurrent loop — R11-identical
__global__ __launch_bounds__(NTHREADS, 1)
void loop_kernel(int ringsel, const float* __restrict__ h0l, const float* __restrict__ c0l,
                 size_t wtoff, int KtotS, int Kin, int lastflag, unsigned barbase) {
    __shared__ float partials[8 * 1152];    // 8 warps x (32 rows x 36 stride)
    __half* ring = ringsel ? g_ringB : g_ringA;
    const __half* WT_l = g_WT + wtoff;

    const int tid = threadIdx.x, cta = blockIdx.x;
    const int wid = tid >> 5, lane = tid & 31;
    const int g = lane >> 2, tig = lane & 3;
    const int rb = tid >> 3, rd = tid & 7;

    uint32_t wreg[8][4][2];
    #pragma unroll
    for (int it = 0; it < 8; ++it)
        #pragma unroll
        for (int nt = 0; nt < 4; ++nt) {
            const __half* p = WT_l + (size_t)(nt * HID + cta * 8 + g) * KtotS
                            + Kin + wid * 128 + it * 16 + 2 * tig;
            wreg[it][nt][0] = *(const uint32_t*)(p);
            wreg[it][nt][1] = *(const uint32_t*)(p + 8);
        }

    float c_state = c0l[rb * HID + cta * 8 + rd];
    const size_t pofs = frag2_off(rb, cta * 8 + rd);
    const size_t cofs = (size_t)wid * 4096 + (size_t)lane * 8;
    unsigned* mycnt = &g_cnt[(cta >> 4) * 32];
    const unsigned* wcnt = &g_cnt[wid * 32];

    ring[pofs] = __float2half(h0l[rb * HID + cta * 8 + rd]);
    __syncthreads();
    if (tid == 0) red_rel(mycnt);
    unsigned wtarget = barbase + 16;

    size_t slot = SLOT_H;
    for (int t = 0; t < NT; ++t, slot += SLOT_H) {
        float z0r[4];
        {
            const float* zp = g_Z0 + ((size_t)(t * NB + rb)) * 4096 + cta * 8 + rd;
            #pragma unroll
            for (int gg = 0; gg < 4; ++gg) z0r[gg] = __ldcg(zp + gg * HID);
        }

        if (lane == 0) { while (ld_acq(wcnt) < wtarget) { } }
        __syncwarp();

        const __half* hp = ring + (slot - SLOT_H) + cofs;
        uint4 areg[16];
        #pragma unroll
        for (int i = 0; i < 16; ++i) areg[i] = __ldcg((const uint4*)(hp + (size_t)i * 256));

        float acc[2][4][4];
        #pragma unroll
        for (int i = 0; i < 2; ++i)
            #pragma unroll
            for (int j = 0; j < 4; ++j)
                #pragma unroll
                for (int k = 0; k < 4; ++k) acc[i][j][k] = 0.f;
        #pragma unroll
        for (int it = 0; it < 8; ++it) {
            const uint32_t* a0 = (const uint32_t*)&areg[it * 2];
            const uint32_t* a1 = (const uint32_t*)&areg[it * 2 + 1];
            #pragma unroll
            for (int nt = 0; nt < 4; ++nt) {
                mma16816(acc[0][nt], a0, wreg[it][nt]);
                mma16816(acc[1][nt], a1, wreg[it][nt]);
            }
        }

        {
            float* P = partials + wid * 1152;
            #pragma unroll
            for (int mt = 0; mt < 2; ++mt)
                #pragma unroll
                for (int nt = 0; nt < 4; ++nt) {
                    int r = mt * 16 + g, cc = nt * 8 + 2 * tig;
                    *(float2*)(P + r * 36 + cc) = make_float2(acc[mt][nt][0], acc[mt][nt][1]);
                    *(float2*)(P + (r + 8) * 36 + cc) = make_float2(acc[mt][nt][2], acc[mt][nt][3]);
                }
        }
        __syncthreads();

        {
            float zi = z0r[0], zf = z0r[1], zg = z0r[2], zo = z0r[3];
            #pragma unroll
            for (int w = 0; w < 8; ++w) {
                const float* P = partials + w * 1152 + rb * 36 + rd;
                zi += P[0]; zf += P[8]; zg += P[16]; zo += P[24];
            }
            float si = sigmoid_fast(zi);
            float sf = sigmoid_fast(zf);
            float so = sigmoid_fast(zo);
            float tg2 = tanh_fast(zg);
            c_state = sf * c_state + si * tg2;
            float h = so * tanh_fast(c_state);
            ring[slot + pofs] = __float2half(h);
            if (lastflag && t == NT - 1) g_hlast[rb * HID + cta * 8 + rd] = h;
        }
        __syncthreads();
        if (tid == 0) red_rel(mycnt);
        wtarget += 16;
    }
}

// dense head v3: 256 blocks (b, oc); 256 threads = 128 output cols x 2 k-halves
__global__ __launch_bounds__(256)
void head_kernel(const float* __restrict__ Wout,
                 const float* __restrict__ bout,
                 float* __restrict__ out) {
    __shared__ float hsh[HID];
    __shared__ float psum[128];
    int b = blockIdx.x;
    for (int i = threadIdx.x; i < HID; i += blockDim.x) hsh[i] = g_hlast[b * HID + i];
    __syncthreads();
    int oc = blockIdx.y;                 // 8 column chunks of 128
    int ol = threadIdx.x & 127;          // output within chunk
    int kh = threadIdx.x >> 7;           // k half (0/1)
    int o = oc * 128 + ol;
    int k0 = kh * 512;
    float s0 = 0.f, s1 = 0.f, s2 = 0.f, s3 = 0.f;
    #pragma unroll 8
    for (int k = k0; k < k0 + 512; k += 4) {
        s0 += hsh[k]     * Wout[(size_t)k * NOUT + o];
        s1 += hsh[k + 1] * Wout[(size_t)(k + 1) * NOUT + o];
        s2 += hsh[k + 2] * Wout[(size_t)(k + 2) * NOUT + o];
        s3 += hsh[k + 3] * Wout[(size_t)(k + 3) * NOUT + o];
    }
    float s = (s0 + s1) + (s2 + s3);
    if (kh == 1) psum[ol] = s;
    __syncthreads();
    if (kh == 0) out[(size_t)b * NOUT + o] = s + psum[ol] + bout[o];
}

extern "C" void kernel_launch(void* const* d_in, const int* in_sizes, int n_in,
                              void* d_out, int out_size) {
    const float* x    = (const float*)d_in[0];
    const float* h0   = (const float*)d_in[1];
    const float* c0   = (const float*)d_in[2];
    const float* W0   = (const float*)d_in[3];
    const float* b0   = (const float*)d_in[4];
    const float* Wl   = (const float*)d_in[5];
    const float* bl   = (const float*)d_in[6];
    const float* Wout = (const float*)d_in[7];
    const float* bout = (const float*)d_in[8];
    float* out = (float*)d_out;

    const size_t HB = (size_t)NB * HID;
    const size_t wt0 = 0;
    const size_t wt1 = (size_t)4096 * 1536;
    const size_t wt2 = wt1 + (size_t)4096 * 2048;
    const size_t wt3 = wt2 + (size_t)4096 * 2048;
    const unsigned per = (unsigned)((NT + 1) * 16);

    reset_kernel<<<1, 256>>>();
    spacer_kernel<<<1, 32>>>();          // launch #2: shifts ncu -s 5 onto loop_kernel
    xfrag_kernel<<<4096, 256>>>(x);
    convT_kernel<<<30720, 256>>>(W0, Wl);

    // layer 0
    gemm_kernel<<<4096, 256>>>(0, XSLOT, wt0, 1536, 512, b0);      // launch #5
    loop_kernel<<<NCTA, NTHREADS>>>(0, h0, c0, wt0, 1536, 512, 0, 0 * per);   // #6 <- profiled
    // layer 1 (input = ringA)
    gemm_kernel<<<4096, 256>>>(1, SLOT_H, wt1, 2048, 1024, bl);
    loop_kernel<<<NCTA, NTHREADS>>>(1, h0 + HB, c0 + HB, wt1, 2048, 1024, 0, 1 * per);
    // layer 2 (input = ringB)
    gemm_kernel<<<4096, 256>>>(2, SLOT_H, wt2, 2048, 1024, bl + 4096);
    loop_kernel<<<NCTA, NTHREADS>>>(0, h0 + 2 * HB, c0 + 2 * HB, wt2, 2048, 1024, 0, 2 * per);
    // layer 3 (input = ringA)
    gemm_kernel<<<4096, 256>>>(1, SLOT_H, wt3, 2048, 1024, bl + 2 * 4096);
    loop_kernel<<<NCTA, NTHREADS>>>(1, h0 + 3 * HB, c0 + 3 * HB, wt3, 2048, 1024, 1, 3 * per);

    head_kernel<<<dim3(NB, 8), 256>>>(Wout, bout, out);
}